// round 1
// baseline (speedup 1.0000x reference)
#include <cuda_runtime.h>

#define N_NODES 32768
#define N_EDGES 262144
#define H 128

// Scratch (device globals — no allocation allowed)
__device__ float g_x[N_NODES * 384];        // interaction MLP output
__device__ float g_filters[N_EDGES * 384];  // filter MLP output * cutoff
__device__ float g_qacc[N_NODES * H];       // scalar message accumulator
__device__ float g_muacc[N_NODES * 384];    // vector message accumulator
__device__ float g_deg[N_NODES];            // in-degree

__device__ __forceinline__ float silu_f(float v) {
    return v / (1.0f + __expf(-v));
}

// ---------------------------------------------------------------------------
// Zero accumulators
// ---------------------------------------------------------------------------
__global__ void zero_kernel() {
    int i = blockIdx.x * blockDim.x + threadIdx.x;
    int stride = gridDim.x * blockDim.x;
    for (int idx = i; idx < N_NODES * 384; idx += stride) g_muacc[idx] = 0.0f;
    for (int idx = i; idx < N_NODES * H; idx += stride) g_qacc[idx] = 0.0f;
    for (int idx = i; idx < N_NODES; idx += stride) g_deg[idx] = 0.0f;
}

// ---------------------------------------------------------------------------
// x = silu(q @ Wi1 + bi1) @ Wi2 + bi2        [N,384]
// 16 rows per block, 128 threads; thread t owns output cols {t, t+128, t+256}
// ---------------------------------------------------------------------------
__global__ void __launch_bounds__(128) compute_x_kernel(
    const float* __restrict__ q,
    const float* __restrict__ Wi1, const float* __restrict__ bi1,
    const float* __restrict__ Wi2, const float* __restrict__ bi2)
{
    __shared__ float qs[16][128];
    __shared__ float h1[16][384];
    const int t = threadIdx.x;
    const int row0 = blockIdx.x * 16;

    #pragma unroll
    for (int r = 0; r < 16; r++)
        qs[r][t] = q[(row0 + r) * H + t];
    __syncthreads();

    float a0[16], a1[16], a2[16];
    {
        float b0 = bi1[t], b1 = bi1[128 + t], b2 = bi1[256 + t];
        #pragma unroll
        for (int r = 0; r < 16; r++) { a0[r] = b0; a1[r] = b1; a2[r] = b2; }
    }
    #pragma unroll 4
    for (int k = 0; k < 128; k++) {
        float w0 = Wi1[k * 384 + t];
        float w1 = Wi1[k * 384 + 128 + t];
        float w2 = Wi1[k * 384 + 256 + t];
        #pragma unroll
        for (int r = 0; r < 16; r++) {
            float a = qs[r][k];
            a0[r] += a * w0; a1[r] += a * w1; a2[r] += a * w2;
        }
    }
    #pragma unroll
    for (int r = 0; r < 16; r++) {
        h1[r][t]       = silu_f(a0[r]);
        h1[r][128 + t] = silu_f(a1[r]);
        h1[r][256 + t] = silu_f(a2[r]);
    }
    __syncthreads();

    {
        float b0 = bi2[t], b1 = bi2[128 + t], b2 = bi2[256 + t];
        #pragma unroll
        for (int r = 0; r < 16; r++) { a0[r] = b0; a1[r] = b1; a2[r] = b2; }
    }
    #pragma unroll 2
    for (int k = 0; k < 384; k++) {
        float w0 = Wi2[k * 384 + t];
        float w1 = Wi2[k * 384 + 128 + t];
        float w2 = Wi2[k * 384 + 256 + t];
        #pragma unroll
        for (int r = 0; r < 16; r++) {
            float a = h1[r][k];
            a0[r] += a * w0; a1[r] += a * w1; a2[r] += a * w2;
        }
    }
    #pragma unroll
    for (int r = 0; r < 16; r++) {
        g_x[(row0 + r) * 384 + t]       = a0[r];
        g_x[(row0 + r) * 384 + 128 + t] = a1[r];
        g_x[(row0 + r) * 384 + 256 + t] = a2[r];
    }
}

// ---------------------------------------------------------------------------
// filters = (silu(rbf @ Wf1 + bf1) @ Wf2 + bf2) * cutoff   [E,384]
// 16 edges per block, 128 threads
// ---------------------------------------------------------------------------
__global__ void __launch_bounds__(128) compute_filters_kernel(
    const float* __restrict__ rbf, const float* __restrict__ cutoff,
    const float* __restrict__ Wf1, const float* __restrict__ bf1,
    const float* __restrict__ Wf2, const float* __restrict__ bf2)
{
    __shared__ float rb[16][20];
    __shared__ float h[16][128];
    __shared__ float co[16];
    const int t = threadIdx.x;
    const int e0 = blockIdx.x * 16;

    for (int idx = t; idx < 16 * 20; idx += 128)
        rb[idx / 20][idx % 20] = rbf[e0 * 20 + idx];
    if (t < 16) co[t] = cutoff[e0 + t];
    __syncthreads();

    {
        float acc[16];
        float b = bf1[t];
        #pragma unroll
        for (int r = 0; r < 16; r++) acc[r] = b;
        #pragma unroll
        for (int k = 0; k < 20; k++) {
            float w = Wf1[k * 128 + t];
            #pragma unroll
            for (int r = 0; r < 16; r++) acc[r] += rb[r][k] * w;
        }
        #pragma unroll
        for (int r = 0; r < 16; r++) h[r][t] = silu_f(acc[r]);
    }
    __syncthreads();

    float a0[16], a1[16], a2[16];
    {
        float b0 = bf2[t], b1 = bf2[128 + t], b2 = bf2[256 + t];
        #pragma unroll
        for (int r = 0; r < 16; r++) { a0[r] = b0; a1[r] = b1; a2[r] = b2; }
    }
    #pragma unroll 4
    for (int k = 0; k < 128; k++) {
        float w0 = Wf2[k * 384 + t];
        float w1 = Wf2[k * 384 + 128 + t];
        float w2 = Wf2[k * 384 + 256 + t];
        #pragma unroll
        for (int r = 0; r < 16; r++) {
            float a = h[r][k];
            a0[r] += a * w0; a1[r] += a * w1; a2[r] += a * w2;
        }
    }
    #pragma unroll
    for (int r = 0; r < 16; r++) {
        float c = co[r];
        g_filters[(e0 + r) * 384 + t]       = a0[r] * c;
        g_filters[(e0 + r) * 384 + 128 + t] = a1[r] * c;
        g_filters[(e0 + r) * 384 + 256 + t] = a2[r] * c;
    }
}

// ---------------------------------------------------------------------------
// Edge messages: gather x[src], mu[src]; scatter-add into qacc/muacc/deg
// One block (128 threads) per edge
// ---------------------------------------------------------------------------
__global__ void __launch_bounds__(128) edge_message_kernel(
    const int* __restrict__ edge_index,
    const float* __restrict__ mu,
    const float* __restrict__ unit_vectors)
{
    const int e = blockIdx.x;
    const int t = threadIdx.x;
    const int tgt = edge_index[e];
    const int src = edge_index[N_EDGES + e];
    const float u0 = unit_vectors[e * 3 + 0];
    const float u1 = unit_vectors[e * 3 + 1];
    const float u2 = unit_vectors[e * 3 + 2];

    const float* xs = g_x + (size_t)src * 384;
    const float* fs = g_filters + (size_t)e * 384;
    const float* ms = mu + (size_t)src * 384;

    float sm = xs[t] * fs[t];
    atomicAdd(&g_qacc[tgt * H + t], sm);

    float xr = xs[128 + t] * fs[128 + t];
    float xm = xs[256 + t] * fs[256 + t];

    atomicAdd(&g_muacc[tgt * 384 + t],       u0 * xr + ms[t]       * xm);
    atomicAdd(&g_muacc[tgt * 384 + 128 + t], u1 * xr + ms[128 + t] * xm);
    atomicAdd(&g_muacc[tgt * 384 + 256 + t], u2 * xr + ms[256 + t] * xm);

    if (t == 0) atomicAdd(&g_deg[tgt], 1.0f);
}

// ---------------------------------------------------------------------------
// Node update + PaiNN mixing, fused. 8 nodes per block, 128 threads.
// mu_w[c] and inner are produced and consumed by the same thread t -> registers.
// ---------------------------------------------------------------------------
__global__ void __launch_bounds__(128) node_mixing_kernel(
    const float* __restrict__ q, const float* __restrict__ mu,
    const float* __restrict__ Wv,
    const float* __restrict__ Ws1, const float* __restrict__ bs1,
    const float* __restrict__ Ws2, const float* __restrict__ bs2,
    float* __restrict__ out)
{
    __shared__ float munew[8][384];
    __shared__ float qn[8][128];
    __shared__ float nrm[8][128];
    __shared__ float hs[8][384];
    const int t = threadIdx.x;
    const int n0 = blockIdx.x * 8;

    #pragma unroll
    for (int r = 0; r < 8; r++) {
        int n = n0 + r;
        float inv = 1.0f / fmaxf(__ldg(&g_deg[n]), 1.0f);
        qn[r][t] = q[n * H + t] + g_qacc[n * H + t] * inv;
        #pragma unroll
        for (int c = 0; c < 3; c++)
            munew[r][c * 128 + t] = mu[n * 384 + c * 128 + t]
                                  + g_muacc[n * 384 + c * 128 + t] * inv;
    }
    __syncthreads();

    // mu_cat = munew @ Wv ; thread t owns mu_v col t (o=t), mu_w col t (o=128+t)
    float v0[8], v1[8], v2[8], w0[8], w1[8], w2[8];
    #pragma unroll
    for (int r = 0; r < 8; r++) {
        v0[r] = v1[r] = v2[r] = 0.0f;
        w0[r] = w1[r] = w2[r] = 0.0f;
    }
    #pragma unroll 4
    for (int f = 0; f < 128; f++) {
        float wv = Wv[f * 256 + t];
        float ww = Wv[f * 256 + 128 + t];
        #pragma unroll
        for (int r = 0; r < 8; r++) {
            float m0 = munew[r][f];
            float m1 = munew[r][128 + f];
            float m2 = munew[r][256 + f];
            v0[r] += m0 * wv; v1[r] += m1 * wv; v2[r] += m2 * wv;
            w0[r] += m0 * ww; w1[r] += m1 * ww; w2[r] += m2 * ww;
        }
    }

    float inner[8];
    #pragma unroll
    for (int r = 0; r < 8; r++) {
        nrm[r][t] = sqrtf(v0[r] * v0[r] + v1[r] * v1[r] + v2[r] * v2[r] + 1e-8f);
        inner[r] = v0[r] * w0[r] + v1[r] * w1[r] + v2[r] * w2[r];
    }
    __syncthreads();

    // delta hidden = silu([qn, nrm] @ Ws1 + bs1)
    float a0[8], a1[8], a2[8];
    {
        float b0 = bs1[t], b1 = bs1[128 + t], b2 = bs1[256 + t];
        #pragma unroll
        for (int r = 0; r < 8; r++) { a0[r] = b0; a1[r] = b1; a2[r] = b2; }
    }
    #pragma unroll 4
    for (int k = 0; k < 128; k++) {
        float x0 = Ws1[k * 384 + t];
        float x1 = Ws1[k * 384 + 128 + t];
        float x2 = Ws1[k * 384 + 256 + t];
        #pragma unroll
        for (int r = 0; r < 8; r++) {
            float a = qn[r][k];
            a0[r] += a * x0; a1[r] += a * x1; a2[r] += a * x2;
        }
    }
    #pragma unroll 4
    for (int k = 0; k < 128; k++) {
        float x0 = Ws1[(128 + k) * 384 + t];
        float x1 = Ws1[(128 + k) * 384 + 128 + t];
        float x2 = Ws1[(128 + k) * 384 + 256 + t];
        #pragma unroll
        for (int r = 0; r < 8; r++) {
            float a = nrm[r][k];
            a0[r] += a * x0; a1[r] += a * x1; a2[r] += a * x2;
        }
    }
    #pragma unroll
    for (int r = 0; r < 8; r++) {
        hs[r][t]       = silu_f(a0[r]);
        hs[r][128 + t] = silu_f(a1[r]);
        hs[r][256 + t] = silu_f(a2[r]);
    }
    __syncthreads();

    // delta = hs @ Ws2 + bs2 ; a0=dq, a1=dmu_scale, a2=dqmu
    {
        float b0 = bs2[t], b1 = bs2[128 + t], b2 = bs2[256 + t];
        #pragma unroll
        for (int r = 0; r < 8; r++) { a0[r] = b0; a1[r] = b1; a2[r] = b2; }
    }
    #pragma unroll 2
    for (int k = 0; k < 384; k++) {
        float x0 = Ws2[k * 384 + t];
        float x1 = Ws2[k * 384 + 128 + t];
        float x2 = Ws2[k * 384 + 256 + t];
        #pragma unroll
        for (int r = 0; r < 8; r++) {
            float a = hs[r][k];
            a0[r] += a * x0; a1[r] += a * x1; a2[r] += a * x2;
        }
    }

    #pragma unroll
    for (int r = 0; r < 8; r++) {
        int n = n0 + r;
        out[n * H + t] = qn[r][t] + a0[r] + a2[r] * inner[r];
        float* mout = out + (size_t)N_NODES * H + (size_t)n * 384;
        mout[t]       = munew[r][t]       + w0[r] * a1[r];
        mout[128 + t] = munew[r][128 + t] + w1[r] * a1[r];
        mout[256 + t] = munew[r][256 + t] + w2[r] * a1[r];
    }
}

// ---------------------------------------------------------------------------
extern "C" void kernel_launch(void* const* d_in, const int* in_sizes, int n_in,
                              void* d_out, int out_size) {
    const float* q            = (const float*)d_in[0];
    const float* mu           = (const float*)d_in[1];
    const int*   edge_index   = (const int*)d_in[2];
    const float* rbf          = (const float*)d_in[3];
    const float* unit_vectors = (const float*)d_in[4];
    const float* cutoff       = (const float*)d_in[5];
    const float* Wi1 = (const float*)d_in[6];
    const float* bi1 = (const float*)d_in[7];
    const float* Wi2 = (const float*)d_in[8];
    const float* bi2 = (const float*)d_in[9];
    const float* Wf1 = (const float*)d_in[10];
    const float* bf1 = (const float*)d_in[11];
    const float* Wf2 = (const float*)d_in[12];
    const float* bf2 = (const float*)d_in[13];
    const float* Wv  = (const float*)d_in[14];
    const float* Ws1 = (const float*)d_in[15];
    const float* bs1 = (const float*)d_in[16];
    const float* Ws2 = (const float*)d_in[17];
    const float* bs2 = (const float*)d_in[18];
    float* out = (float*)d_out;

    zero_kernel<<<1024, 256>>>();
    compute_x_kernel<<<N_NODES / 16, 128>>>(q, Wi1, bi1, Wi2, bi2);
    compute_filters_kernel<<<N_EDGES / 16, 128>>>(rbf, cutoff, Wf1, bf1, Wf2, bf2);
    edge_message_kernel<<<N_EDGES, 128>>>(edge_index, mu, unit_vectors);
    node_mixing_kernel<<<N_NODES / 8, 128>>>(q, mu, Wv, Ws1, bs1, Ws2, bs2, out);
}